// round 4
// baseline (speedup 1.0000x reference)
#include <cuda_runtime.h>
#include <cuda_bf16.h>
#include <math_constants.h>

// Problem constants
#define B_  16
#define T_  2048
#define C_  1024
#define D_  64

// Scratch for Q, K, V projections (8 MB each). Device globals: allocation-free.
__device__ float g_Q[B_ * T_ * D_];
__device__ float g_K[B_ * T_ * D_];
__device__ float g_V[B_ * T_ * D_];

// ---------------------------------------------------------------------------
// Kernel 1: fused QKV projection.
// X [32768, 1024] @ {Wq,Wk,Wv} [1024, 64] -> g_Q/g_K/g_V [32768, 64]
// Block: 64 rows of X, all 64 cols, all 3 matrices. 256 threads (16x16),
// each thread owns a 4x4 output tile per matrix (48 accumulators).
// ---------------------------------------------------------------------------
#define QKV_BM 64
#define QKV_KC 32

__global__ __launch_bounds__(256)
void qkv_kernel(const float* __restrict__ x,
                const float* __restrict__ Wq,
                const float* __restrict__ Wk,
                const float* __restrict__ Wv) {
    __shared__ float Xs[QKV_BM][QKV_KC];      // 8 KB
    __shared__ float Ws[3][QKV_KC][D_];       // 24 KB

    const int m0 = blockIdx.x * QKV_BM;
    const int tid = threadIdx.x;
    const int tx = tid & 15;       // 0..15 -> 4 output cols each
    const int ty = tid >> 4;       // 0..15 -> 4 output rows each

    float acc[3][4][4];
#pragma unroll
    for (int m = 0; m < 3; m++)
#pragma unroll
        for (int i = 0; i < 4; i++)
#pragma unroll
            for (int j = 0; j < 4; j++) acc[m][i][j] = 0.0f;

    for (int k0 = 0; k0 < C_; k0 += QKV_KC) {
        // Load X tile: 64x32 floats = 512 float4, 2 per thread
#pragma unroll
        for (int it = 0; it < 2; it++) {
            int i  = tid + it * 256;
            int r  = i >> 3;           // / (KC/4)
            int c4 = i & 7;
            reinterpret_cast<float4*>(&Xs[r][0])[c4] =
                reinterpret_cast<const float4*>(x + (size_t)(m0 + r) * C_ + k0)[c4];
        }
        // Load W tiles: 3x32x64 floats = 1536 float4, 6 per thread
#pragma unroll
        for (int it = 0; it < 6; it++) {
            int i   = tid + it * 256;
            int mat = i >> 9;          // / 512
            int rem = i & 511;
            int r   = rem >> 4;        // / 16
            int c4  = rem & 15;
            const float* Wp = (mat == 0) ? Wq : ((mat == 1) ? Wk : Wv);
            reinterpret_cast<float4*>(&Ws[mat][r][0])[c4] =
                reinterpret_cast<const float4*>(Wp + (size_t)(k0 + r) * D_)[c4];
        }
        __syncthreads();

#pragma unroll 4
        for (int k = 0; k < QKV_KC; k++) {
            float xv[4];
#pragma unroll
            for (int i = 0; i < 4; i++) xv[i] = Xs[4 * ty + i][k];
#pragma unroll
            for (int m = 0; m < 3; m++) {
                float4 wv = *reinterpret_cast<const float4*>(&Ws[m][k][4 * tx]);
#pragma unroll
                for (int i = 0; i < 4; i++) {
                    acc[m][i][0] += xv[i] * wv.x;
                    acc[m][i][1] += xv[i] * wv.y;
                    acc[m][i][2] += xv[i] * wv.z;
                    acc[m][i][3] += xv[i] * wv.w;
                }
            }
        }
        __syncthreads();
    }

    // Epilogue: coalesced float4 stores
#pragma unroll
    for (int m = 0; m < 3; m++) {
        float* dst = (m == 0) ? g_Q : ((m == 1) ? g_K : g_V);
#pragma unroll
        for (int i = 0; i < 4; i++) {
            float4 v = make_float4(acc[m][i][0], acc[m][i][1], acc[m][i][2], acc[m][i][3]);
            *reinterpret_cast<float4*>(&dst[(size_t)(m0 + 4 * ty + i) * D_ + 4 * tx]) = v;
        }
    }
}

// ---------------------------------------------------------------------------
// Kernel 2: causal flash attention, fp32, 64x64 tiles, D=64.
// Grid: (T/64, B). 256 threads (16x16); thread owns 4 rows x 4 cols of S/O.
// Shared: Qs (16K) + KV union buffer (K^T then V, 16K) + Ps (16K) = 48 KB.
// Online softmax with shuffle reductions across the 16-lane tx groups.
// ---------------------------------------------------------------------------
#define ATT_BM 64

__global__ __launch_bounds__(256)
void attn_kernel(float* __restrict__ out) {
    __shared__ float Qs[ATT_BM][D_];   // Qs[row][k], pre-scaled by 1/32
    __shared__ float KV[ATT_BM][D_];   // phase 1: K^T as KV[k][n]; phase 2: V as KV[n][d]
    __shared__ float Ps[ATT_BM][D_];   // probabilities P[row][n]

    const int qt  = blockIdx.x;             // query tile
    const int b   = blockIdx.y;
    const int q0  = qt * ATT_BM;
    const int tid = threadIdx.x;
    const int tx  = tid & 15;               // col group
    const int ty  = tid >> 4;               // row group

    const float inv_sqrt_c = 1.0f / 32.0f;  // 1/sqrt(1024)

    // Load Q tile, pre-scaled. 4096 floats = 1024 float4, 4 per thread.
    const float* Qg = g_Q + ((size_t)b * T_ + q0) * D_;
#pragma unroll
    for (int it = 0; it < 4; it++) {
        int i  = tid + it * 256;
        int r  = i >> 4;
        int c4 = i & 15;
        float4 v = reinterpret_cast<const float4*>(Qg + (size_t)r * D_)[c4];
        v.x *= inv_sqrt_c; v.y *= inv_sqrt_c; v.z *= inv_sqrt_c; v.w *= inv_sqrt_c;
        reinterpret_cast<float4*>(&Qs[r][0])[c4] = v;
    }

    float m_run[4], l_run[4], o[4][4];
#pragma unroll
    for (int i = 0; i < 4; i++) {
        m_run[i] = -CUDART_INF_F;
        l_run[i] = 0.0f;
#pragma unroll
        for (int j = 0; j < 4; j++) o[i][j] = 0.0f;
    }

    for (int jt = 0; jt <= qt; jt++) {
        const int t0 = jt * ATT_BM;
        __syncthreads();  // prior PV reads of KV done (also covers Qs load on jt=0)

        // Load K tile transposed: KV[k][n] = K[b][t0+n][k]
        {
            const float* Kg = g_K + ((size_t)b * T_ + t0) * D_;
            int k4 = tid & 15;      // which float4 along d
            int nb = tid >> 4;      // base n
#pragma unroll
            for (int it = 0; it < 4; it++) {
                int n = nb + 16 * it;
                float4 kd = reinterpret_cast<const float4*>(Kg + (size_t)n * D_)[k4];
                KV[4 * k4 + 0][n] = kd.x;
                KV[4 * k4 + 1][n] = kd.y;
                KV[4 * k4 + 2][n] = kd.z;
                KV[4 * k4 + 3][n] = kd.w;
            }
        }
        __syncthreads();

        // S = Q @ K^T for this tile: s[i][j], rows 4ty+i, cols 4tx+j
        float s[4][4];
#pragma unroll
        for (int i = 0; i < 4; i++)
#pragma unroll
            for (int j = 0; j < 4; j++) s[i][j] = 0.0f;

#pragma unroll 4
        for (int k = 0; k < D_; k += 4) {
            float4 qv[4], kv[4];
#pragma unroll
            for (int i = 0; i < 4; i++)
                qv[i] = *reinterpret_cast<const float4*>(&Qs[4 * ty + i][k]);
#pragma unroll
            for (int e = 0; e < 4; e++)
                kv[e] = *reinterpret_cast<const float4*>(&KV[k + e][4 * tx]);
#pragma unroll
            for (int i = 0; i < 4; i++) {
                float q0v = qv[i].x, q1v = qv[i].y, q2v = qv[i].z, q3v = qv[i].w;
                s[i][0] += q0v * kv[0].x + q1v * kv[1].x + q2v * kv[2].x + q3v * kv[3].x;
                s[i][1] += q0v * kv[0].y + q1v * kv[1].y + q2v * kv[2].y + q3v * kv[3].y;
                s[i][2] += q0v * kv[0].z + q1v * kv[1].z + q2v * kv[2].z + q3v * kv[3].z;
                s[i][3] += q0v * kv[0].w + q1v * kv[1].w + q2v * kv[2].w + q3v * kv[3].w;
            }
        }

        // Causal mask on the diagonal tile (t0 == q0): mask col > row
        if (jt == qt) {
#pragma unroll
            for (int i = 0; i < 4; i++) {
                int row = 4 * ty + i;
#pragma unroll
                for (int j = 0; j < 4; j++) {
                    int col = 4 * tx + j;
                    if (col > row) s[i][j] = -CUDART_INF_F;
                }
            }
        }

        // Online softmax update + write P to shared
#pragma unroll
        for (int i = 0; i < 4; i++) {
            float tmax = fmaxf(fmaxf(s[i][0], s[i][1]), fmaxf(s[i][2], s[i][3]));
#pragma unroll
            for (int off = 8; off > 0; off >>= 1)
                tmax = fmaxf(tmax, __shfl_xor_sync(0xffffffffu, tmax, off));
            float mn = fmaxf(m_run[i], tmax);
            float p0 = __expf(s[i][0] - mn);
            float p1 = __expf(s[i][1] - mn);
            float p2 = __expf(s[i][2] - mn);
            float p3 = __expf(s[i][3] - mn);
            float tsum = p0 + p1 + p2 + p3;
#pragma unroll
            for (int off = 8; off > 0; off >>= 1)
                tsum += __shfl_xor_sync(0xffffffffu, tsum, off);
            float scale = __expf(m_run[i] - mn);  // 0 when m_run == -inf
            l_run[i] = l_run[i] * scale + tsum;
            m_run[i] = mn;
#pragma unroll
            for (int j = 0; j < 4; j++) o[i][j] *= scale;
            *reinterpret_cast<float4*>(&Ps[4 * ty + i][4 * tx]) = make_float4(p0, p1, p2, p3);
        }
        __syncthreads();  // Ps visible; K^T reads finished

        // Load V tile (natural layout): KV[n][d] = V[b][t0+n][d]
        {
            const float* Vg = g_V + ((size_t)b * T_ + t0) * D_;
#pragma unroll
            for (int it = 0; it < 4; it++) {
                int i  = tid + it * 256;
                int r  = i >> 4;
                int c4 = i & 15;
                reinterpret_cast<float4*>(&KV[r][0])[c4] =
                    reinterpret_cast<const float4*>(Vg + (size_t)r * D_)[c4];
            }
        }
        __syncthreads();

        // O += P @ V : contract over n
#pragma unroll 4
        for (int n = 0; n < ATT_BM; n += 4) {
            float4 pv[4], vv[4];
#pragma unroll
            for (int i = 0; i < 4; i++)
                pv[i] = *reinterpret_cast<const float4*>(&Ps[4 * ty + i][n]);
#pragma unroll
            for (int e = 0; e < 4; e++)
                vv[e] = *reinterpret_cast<const float4*>(&KV[n + e][4 * tx]);
#pragma unroll
            for (int i = 0; i < 4; i++) {
                float a0 = pv[i].x, a1 = pv[i].y, a2 = pv[i].z, a3 = pv[i].w;
                o[i][0] += a0 * vv[0].x + a1 * vv[1].x + a2 * vv[2].x + a3 * vv[3].x;
                o[i][1] += a0 * vv[0].y + a1 * vv[1].y + a2 * vv[2].y + a3 * vv[3].y;
                o[i][2] += a0 * vv[0].z + a1 * vv[1].z + a2 * vv[2].z + a3 * vv[3].z;
                o[i][3] += a0 * vv[0].w + a1 * vv[1].w + a2 * vv[2].w + a3 * vv[3].w;
            }
        }
    }

    // Final normalize + store
    float* Og = out + ((size_t)b * T_ + q0) * D_;
#pragma unroll
    for (int i = 0; i < 4; i++) {
        float inv_l = 1.0f / l_run[i];
        float4 v = make_float4(o[i][0] * inv_l, o[i][1] * inv_l,
                               o[i][2] * inv_l, o[i][3] * inv_l);
        *reinterpret_cast<float4*>(&Og[(size_t)(4 * ty + i) * D_ + 4 * tx]) = v;
    }
}

// ---------------------------------------------------------------------------
extern "C" void kernel_launch(void* const* d_in, const int* in_sizes, int n_in,
                              void* d_out, int out_size) {
    const float* x  = (const float*)d_in[0];
    const float* Wq = (const float*)d_in[1];
    const float* Wk = (const float*)d_in[2];
    const float* Wv = (const float*)d_in[3];
    float* out = (float*)d_out;

    qkv_kernel<<<(B_ * T_) / QKV_BM, 256>>>(x, Wq, Wk, Wv);
    attn_kernel<<<dim3(T_ / ATT_BM, B_), 256>>>(out);
}

// round 5
// speedup vs baseline: 1.6489x; 1.6489x over previous
#include <cuda_runtime.h>
#include <cuda_bf16.h>
#include <math_constants.h>

// Problem constants
#define B_  16
#define T_  2048
#define C_  1024
#define D_  64

// Scratch for Q, K, V projections (8 MB each). Device globals: allocation-free.
__device__ float g_Q[B_ * T_ * D_];
__device__ float g_K[B_ * T_ * D_];
__device__ float g_V[B_ * T_ * D_];

// ---------------------------------------------------------------------------
// tf32 helpers
// ---------------------------------------------------------------------------
__device__ __forceinline__ unsigned f2tf32(float a) {
    unsigned r;
    asm("cvt.rna.tf32.f32 %0, %1;" : "=r"(r) : "f"(a));
    return r;
}

// Split fp32 into tf32 hi + tf32 lo (hi is exact as fp32, lo = round(a - hi)).
__device__ __forceinline__ void split_tf32(float a, unsigned& hi, unsigned& lo) {
    asm("cvt.rna.tf32.f32 %0, %1;" : "=r"(hi) : "f"(a));
    float r = a - __uint_as_float(hi);
    asm("cvt.rna.tf32.f32 %0, %1;" : "=r"(lo) : "f"(r));
}

// D += A * B, m16n8k8 tf32, fp32 accumulate. c[4] in-place.
__device__ __forceinline__ void mma_tf32(float* c, const unsigned* a,
                                         unsigned b0, unsigned b1) {
    asm volatile(
        "mma.sync.aligned.m16n8k8.row.col.f32.tf32.tf32.f32 "
        "{%0,%1,%2,%3}, {%4,%5,%6,%7}, {%8,%9}, {%0,%1,%2,%3};\n"
        : "+f"(c[0]), "+f"(c[1]), "+f"(c[2]), "+f"(c[3])
        : "r"(a[0]), "r"(a[1]), "r"(a[2]), "r"(a[3]), "r"(b0), "r"(b1));
}

// ---------------------------------------------------------------------------
// Kernel 1: QKV projection with 3xTF32 (full fp32-grade accuracy).
// X [32768,1024] @ W [1024,64] -> g_{Q,K,V}. grid = (M/128, 3), 256 threads.
// Warp w owns rows [16w,16w+16) x all 64 cols = 8 n8-tiles (32 fp32 acc).
// ---------------------------------------------------------------------------
#define PBM 128
#define PKC 32

__global__ __launch_bounds__(256)
void qkv_mma_kernel(const float* __restrict__ x,
                    const float* __restrict__ Wq,
                    const float* __restrict__ Wk,
                    const float* __restrict__ Wv) {
    __shared__ float Xs[PBM][36];   // pad 36: fragment banks = (4g+tig) -> conflict-free
    __shared__ float Ws[PKC][72];   // pad 72: fragment banks = (8tig+g) -> conflict-free

    const int mat = blockIdx.y;
    const float* __restrict__ W = (mat == 0) ? Wq : (mat == 1) ? Wk : Wv;
    float* dst = (mat == 0) ? g_Q : (mat == 1) ? g_K : g_V;

    const int m0   = blockIdx.x * PBM;
    const int tid  = threadIdx.x;
    const int w    = tid >> 5;
    const int lane = tid & 31;
    const int g    = lane >> 2;   // 0..7
    const int tig  = lane & 3;    // 0..3

    float acc[8][4];
#pragma unroll
    for (int j = 0; j < 8; j++)
#pragma unroll
        for (int e = 0; e < 4; e++) acc[j][e] = 0.0f;

    const int r0 = 16 * w + g;
    const int r1 = r0 + 8;

    for (int k0 = 0; k0 < C_; k0 += PKC) {
        // Stage X tile 128x32: 1024 float4, 4 per thread
#pragma unroll
        for (int it = 0; it < 4; it++) {
            int i  = tid + 256 * it;
            int r  = i >> 3;
            int c4 = i & 7;
            float4 v = *reinterpret_cast<const float4*>(
                x + (size_t)(m0 + r) * C_ + k0 + 4 * c4);
            *reinterpret_cast<float4*>(&Xs[r][4 * c4]) = v;
        }
        // Stage W tile 32x64: 512 float4, 2 per thread
#pragma unroll
        for (int it = 0; it < 2; it++) {
            int i  = tid + 256 * it;
            int r  = i >> 4;
            int c4 = i & 15;
            float4 v = *reinterpret_cast<const float4*>(
                W + (size_t)(k0 + r) * D_ + 4 * c4);
            *reinterpret_cast<float4*>(&Ws[r][4 * c4]) = v;
        }
        __syncthreads();

#pragma unroll
        for (int ks = 0; ks < 4; ks++) {
            const int kc = 8 * ks;
            unsigned ahi[4], alo[4];
            split_tf32(Xs[r0][kc + tig],     ahi[0], alo[0]);
            split_tf32(Xs[r1][kc + tig],     ahi[1], alo[1]);
            split_tf32(Xs[r0][kc + tig + 4], ahi[2], alo[2]);
            split_tf32(Xs[r1][kc + tig + 4], ahi[3], alo[3]);
#pragma unroll
            for (int j = 0; j < 8; j++) {
                unsigned bh0, bl0, bh1, bl1;
                split_tf32(Ws[kc + tig][8 * j + g],     bh0, bl0);
                split_tf32(Ws[kc + tig + 4][8 * j + g], bh1, bl1);
                mma_tf32(acc[j], ahi, bh0, bh1);
                mma_tf32(acc[j], alo, bh0, bh1);
                mma_tf32(acc[j], ahi, bl0, bl1);
            }
        }
        __syncthreads();
    }

    // Epilogue: float2 stores (C-fragment cols are 2tig, 2tig+1 adjacent)
#pragma unroll
    for (int j = 0; j < 8; j++) {
        int c = 8 * j + 2 * tig;
        *reinterpret_cast<float2*>(&dst[(size_t)(m0 + r0) * D_ + c]) =
            make_float2(acc[j][0], acc[j][1]);
        *reinterpret_cast<float2*>(&dst[(size_t)(m0 + r1) * D_ + c]) =
            make_float2(acc[j][2], acc[j][3]);
    }
}

// ---------------------------------------------------------------------------
// Kernel 2: causal flash attention on tensor cores.
// 128 threads = 4 warps; warp w owns rows [16w,16w+16) of a 64-row Q tile.
// QK^T: single-pass tf32 (error enters only via softmax logits).
// P@V : 3xTF32 split (dominant accuracy term removed).
// Smem: KP (K tile, then P tile, 64x68) + Vs (64x72) = 35 KB static.
// Reversed blockIdx.x -> longest causal blocks launch first.
// ---------------------------------------------------------------------------
__global__ __launch_bounds__(128)
void attn_mma_kernel(float* __restrict__ out) {
    __shared__ float KP[64][68];  // K frags: bank (4g+tig); P frags: bank (4g+tig)
    __shared__ float Vs[64][72];  // V frags: bank (8tig+g)

    const int qt = (int)gridDim.x - 1 - (int)blockIdx.x;  // longest-first
    const int b  = blockIdx.y;
    const int q0 = qt * 64;

    const int tid  = threadIdx.x;
    const int w    = tid >> 5;
    const int lane = tid & 31;
    const int g    = lane >> 2;
    const int tig  = lane & 3;
    const int r0   = 16 * w + g;   // warp-local row (also global row - q0)
    const int r1   = r0 + 8;

    // Stage Q tile through KP, then extract tf32 fragments (scaled by 1/32)
    {
        const float* Qg = g_Q + ((size_t)b * T_ + q0) * D_;
#pragma unroll
        for (int it = 0; it < 8; it++) {
            int i  = tid + 128 * it;
            int r  = i >> 4;
            int c4 = i & 15;
            *reinterpret_cast<float4*>(&KP[r][4 * c4]) =
                *reinterpret_cast<const float4*>(&Qg[(size_t)r * D_ + 4 * c4]);
        }
    }
    __syncthreads();

    const float inv_sqrt_c = 1.0f / 32.0f;
    unsigned qf[8][4];
#pragma unroll
    for (int ks = 0; ks < 8; ks++) {
        const int kc = 8 * ks;
        qf[ks][0] = f2tf32(inv_sqrt_c * KP[r0][kc + tig]);
        qf[ks][1] = f2tf32(inv_sqrt_c * KP[r1][kc + tig]);
        qf[ks][2] = f2tf32(inv_sqrt_c * KP[r0][kc + tig + 4]);
        qf[ks][3] = f2tf32(inv_sqrt_c * KP[r1][kc + tig + 4]);
    }

    float oacc[8][4];
#pragma unroll
    for (int j = 0; j < 8; j++)
#pragma unroll
        for (int e = 0; e < 4; e++) oacc[j][e] = 0.0f;
    float mr[2] = {-CUDART_INF_F, -CUDART_INF_F};
    float lr[2] = {0.0f, 0.0f};

    for (int jt = 0; jt <= qt; jt++) {
        __syncthreads();  // previous iter's P/V reads (and Q frag extraction) done

        // Load K and V tiles (64x64 each): 8 float4 per thread per tile
        {
            const float* Kg = g_K + ((size_t)b * T_ + jt * 64) * D_;
            const float* Vg = g_V + ((size_t)b * T_ + jt * 64) * D_;
#pragma unroll
            for (int it = 0; it < 8; it++) {
                int i  = tid + 128 * it;
                int r  = i >> 4;
                int c4 = i & 15;
                *reinterpret_cast<float4*>(&KP[r][4 * c4]) =
                    *reinterpret_cast<const float4*>(&Kg[(size_t)r * D_ + 4 * c4]);
                *reinterpret_cast<float4*>(&Vs[r][4 * c4]) =
                    *reinterpret_cast<const float4*>(&Vg[(size_t)r * D_ + 4 * c4]);
            }
        }
        __syncthreads();

        // S = Q @ K^T (single-pass tf32)
        float sacc[8][4];
#pragma unroll
        for (int j = 0; j < 8; j++)
#pragma unroll
            for (int e = 0; e < 4; e++) sacc[j][e] = 0.0f;

#pragma unroll
        for (int ks = 0; ks < 8; ks++) {
            const int kc = 8 * ks;
#pragma unroll
            for (int j = 0; j < 8; j++) {
                unsigned b0 = f2tf32(KP[8 * j + g][kc + tig]);
                unsigned b1 = f2tf32(KP[8 * j + g][kc + tig + 4]);
                mma_tf32(sacc[j], qf[ks], b0, b1);
            }
        }

        // Causal mask on the diagonal tile (q0 == t0 here)
        if (jt == qt) {
#pragma unroll
            for (int j = 0; j < 8; j++) {
                int c = 8 * j + 2 * tig;
                if (c     > r0) sacc[j][0] = -CUDART_INF_F;
                if (c + 1 > r0) sacc[j][1] = -CUDART_INF_F;
                if (c     > r1) sacc[j][2] = -CUDART_INF_F;
                if (c + 1 > r1) sacc[j][3] = -CUDART_INF_F;
            }
        }

        // Online softmax: thread owns 16 logits of row r0 (c0,c1) and r1 (c2,c3);
        // the other 48 cols of each row live in the same lane quad -> shfl reduce.
#pragma unroll
        for (int r = 0; r < 2; r++) {
            const int e0 = 2 * r, e1 = 2 * r + 1;
            float mx = -CUDART_INF_F;
#pragma unroll
            for (int j = 0; j < 8; j++)
                mx = fmaxf(mx, fmaxf(sacc[j][e0], sacc[j][e1]));
            mx = fmaxf(mx, __shfl_xor_sync(0xffffffffu, mx, 1));
            mx = fmaxf(mx, __shfl_xor_sync(0xffffffffu, mx, 2));
            float mn  = fmaxf(mr[r], mx);
            float sum = 0.0f;
#pragma unroll
            for (int j = 0; j < 8; j++) {
                float p0 = __expf(sacc[j][e0] - mn);
                float p1 = __expf(sacc[j][e1] - mn);
                sacc[j][e0] = p0;
                sacc[j][e1] = p1;
                sum += p0 + p1;
            }
            sum += __shfl_xor_sync(0xffffffffu, sum, 1);
            sum += __shfl_xor_sync(0xffffffffu, sum, 2);
            float resc = __expf(mr[r] - mn);  // 0 when mr == -inf
            lr[r] = lr[r] * resc + sum;
            mr[r] = mn;
#pragma unroll
            for (int j = 0; j < 8; j++) {
                oacc[j][e0] *= resc;
                oacc[j][e1] *= resc;
            }
        }

        __syncthreads();  // all warps done reading K from KP

        // Write P into KP (C-fragment layout -> natural row-major)
#pragma unroll
        for (int j = 0; j < 8; j++) {
            int c = 8 * j + 2 * tig;
            *reinterpret_cast<float2*>(&KP[r0][c]) = make_float2(sacc[j][0], sacc[j][1]);
            *reinterpret_cast<float2*>(&KP[r1][c]) = make_float2(sacc[j][2], sacc[j][3]);
        }
        __syncthreads();

        // O += P @ V with 3xTF32 split
#pragma unroll
        for (int ks = 0; ks < 8; ks++) {
            const int kc = 8 * ks;
            unsigned ah[4], al[4];
            split_tf32(KP[r0][kc + tig],     ah[0], al[0]);
            split_tf32(KP[r1][kc + tig],     ah[1], al[1]);
            split_tf32(KP[r0][kc + tig + 4], ah[2], al[2]);
            split_tf32(KP[r1][kc + tig + 4], ah[3], al[3]);
#pragma unroll
            for (int j = 0; j < 8; j++) {
                unsigned bh0, bl0, bh1, bl1;
                split_tf32(Vs[kc + tig][8 * j + g],     bh0, bl0);
                split_tf32(Vs[kc + tig + 4][8 * j + g], bh1, bl1);
                mma_tf32(oacc[j], ah, bh0, bh1);
                mma_tf32(oacc[j], al, bh0, bh1);
                mma_tf32(oacc[j], ah, bl0, bl1);
            }
        }
    }

    // Final normalize + store
    const float inv0 = 1.0f / lr[0];
    const float inv1 = 1.0f / lr[1];
    float* Og = out + ((size_t)b * T_ + q0) * D_;
#pragma unroll
    for (int j = 0; j < 8; j++) {
        int c = 8 * j + 2 * tig;
        *reinterpret_cast<float2*>(&Og[(size_t)r0 * D_ + c]) =
            make_float2(oacc[j][0] * inv0, oacc[j][1] * inv0);
        *reinterpret_cast<float2*>(&Og[(size_t)r1 * D_ + c]) =
            make_float2(oacc[j][2] * inv1, oacc[j][3] * inv1);
    }
}

// ---------------------------------------------------------------------------
extern "C" void kernel_launch(void* const* d_in, const int* in_sizes, int n_in,
                              void* d_out, int out_size) {
    const float* x  = (const float*)d_in[0];
    const float* Wq = (const float*)d_in[1];
    const float* Wk = (const float*)d_in[2];
    const float* Wv = (const float*)d_in[3];
    float* out = (float*)d_out;

    qkv_mma_kernel<<<dim3((B_ * T_) / PBM, 3), 256>>>(x, Wq, Wk, Wv);
    attn_mma_kernel<<<dim3(T_ / 64, B_), 128>>>(out);
}

// round 6
// speedup vs baseline: 2.1438x; 1.3001x over previous
#include <cuda_runtime.h>
#include <cuda_bf16.h>
#include <math_constants.h>

// Problem constants
#define B_  16
#define T_  2048
#define C_  1024
#define D_  64

// Scratch (device globals: allocation-free).
// g_Q: tf32-pre-rounded, pre-scaled by 1/sqrt(C). g_K, g_V: tf32-pre-rounded.
__device__ float g_Q[B_ * T_ * D_];
__device__ float g_K[B_ * T_ * D_];
__device__ float g_V[B_ * T_ * D_];
// Pre-split W (hi/lo tf32 pair), filled by wsplit_kernel each call.
__device__ float g_Whi[3][C_ * D_];
__device__ float g_Wlo[3][C_ * D_];

// ---------------------------------------------------------------------------
// tf32 helpers
// ---------------------------------------------------------------------------
__device__ __forceinline__ unsigned f2tf32(float a) {
    unsigned r;
    asm("cvt.rna.tf32.f32 %0, %1;" : "=r"(r) : "f"(a));
    return r;
}

// Split fp32 into tf32 hi + tf32 lo (hi exact in fp32; lo = round(a - hi)).
__device__ __forceinline__ void split_tf32(float a, unsigned& hi, unsigned& lo) {
    asm("cvt.rna.tf32.f32 %0, %1;" : "=r"(hi) : "f"(a));
    float r = a - __uint_as_float(hi);
    asm("cvt.rna.tf32.f32 %0, %1;" : "=r"(lo) : "f"(r));
}

// D += A * B, m16n8k8 tf32, fp32 accumulate. c[4] in-place.
__device__ __forceinline__ void mma_tf32(float* c, const unsigned* a,
                                         unsigned b0, unsigned b1) {
    asm volatile(
        "mma.sync.aligned.m16n8k8.row.col.f32.tf32.tf32.f32 "
        "{%0,%1,%2,%3}, {%4,%5,%6,%7}, {%8,%9}, {%0,%1,%2,%3};\n"
        : "+f"(c[0]), "+f"(c[1]), "+f"(c[2]), "+f"(c[3])
        : "r"(a[0]), "r"(a[1]), "r"(a[2]), "r"(a[3]), "r"(b0), "r"(b1));
}

// ---------------------------------------------------------------------------
// Kernel 0: split the three W matrices into tf32 hi/lo once per call.
// 3 * 65536 elements, 768 blocks x 256 threads.
// ---------------------------------------------------------------------------
__global__ __launch_bounds__(256)
void wsplit_kernel(const float* __restrict__ Wq,
                   const float* __restrict__ Wk,
                   const float* __restrict__ Wv) {
    int i   = blockIdx.x * 256 + threadIdx.x;
    int mat = i / (C_ * D_);
    int e   = i - mat * (C_ * D_);
    const float* W = (mat == 0) ? Wq : (mat == 1) ? Wk : Wv;
    unsigned hi, lo;
    split_tf32(W[e], hi, lo);
    g_Whi[mat][e] = __uint_as_float(hi);
    g_Wlo[mat][e] = __uint_as_float(lo);
}

// ---------------------------------------------------------------------------
// Kernel 1: QKV projection, 3xTF32 with pre-split W (no cvt in inner loop).
// X [32768,1024] @ W [1024,64]. grid = (M/128, 3), 256 threads.
// Epilogue pre-rounds outputs to tf32 (Q additionally scaled by 1/32).
// ---------------------------------------------------------------------------
#define PBM 128
#define PKC 32

__global__ __launch_bounds__(256)
void qkv_mma_kernel(const float* __restrict__ x) {
    __shared__ float Xs [PBM][36];   // fp32; fragment banks (4g+tig) conflict-free
    __shared__ float Whs[PKC][72];   // tf32 bits; fragment banks (8tig+g) conflict-free
    __shared__ float Wls[PKC][72];

    const int mat = blockIdx.y;
    const float* __restrict__ Whig = g_Whi[mat];
    const float* __restrict__ Wlog = g_Wlo[mat];
    float* dst = (mat == 0) ? g_Q : (mat == 1) ? g_K : g_V;

    const int m0   = blockIdx.x * PBM;
    const int tid  = threadIdx.x;
    const int w    = tid >> 5;
    const int lane = tid & 31;
    const int g    = lane >> 2;   // 0..7
    const int tig  = lane & 3;    // 0..3

    float acc[8][4];
#pragma unroll
    for (int j = 0; j < 8; j++)
#pragma unroll
        for (int e = 0; e < 4; e++) acc[j][e] = 0.0f;

    const int r0 = 16 * w + g;
    const int r1 = r0 + 8;

    for (int k0 = 0; k0 < C_; k0 += PKC) {
        // Stage X tile 128x32: 1024 float4, 4 per thread
#pragma unroll
        for (int it = 0; it < 4; it++) {
            int i  = tid + 256 * it;
            int r  = i >> 3;
            int c4 = i & 7;
            float4 v = *reinterpret_cast<const float4*>(
                x + (size_t)(m0 + r) * C_ + k0 + 4 * c4);
            *reinterpret_cast<float4*>(&Xs[r][4 * c4]) = v;
        }
        // Stage Whi/Wlo tiles 32x64: 512 float4 each, 2 per thread each
#pragma unroll
        for (int it = 0; it < 2; it++) {
            int i  = tid + 256 * it;
            int r  = i >> 4;
            int c4 = i & 15;
            size_t off = (size_t)(k0 + r) * D_ + 4 * c4;
            *reinterpret_cast<float4*>(&Whs[r][4 * c4]) =
                *reinterpret_cast<const float4*>(Whig + off);
            *reinterpret_cast<float4*>(&Wls[r][4 * c4]) =
                *reinterpret_cast<const float4*>(Wlog + off);
        }
        __syncthreads();

#pragma unroll
        for (int ks = 0; ks < 4; ks++) {
            const int kc = 8 * ks;
            unsigned ahi[4], alo[4];
            split_tf32(Xs[r0][kc + tig],     ahi[0], alo[0]);
            split_tf32(Xs[r1][kc + tig],     ahi[1], alo[1]);
            split_tf32(Xs[r0][kc + tig + 4], ahi[2], alo[2]);
            split_tf32(Xs[r1][kc + tig + 4], ahi[3], alo[3]);
#pragma unroll
            for (int j = 0; j < 8; j++) {
                unsigned bh0 = __float_as_uint(Whs[kc + tig][8 * j + g]);
                unsigned bh1 = __float_as_uint(Whs[kc + tig + 4][8 * j + g]);
                unsigned bl0 = __float_as_uint(Wls[kc + tig][8 * j + g]);
                unsigned bl1 = __float_as_uint(Wls[kc + tig + 4][8 * j + g]);
                mma_tf32(acc[j], ahi, bh0, bh1);
                mma_tf32(acc[j], alo, bh0, bh1);
                mma_tf32(acc[j], ahi, bl0, bl1);
            }
        }
        __syncthreads();
    }

    // Epilogue: pre-round to tf32 (Q also pre-scaled by 1/sqrt(C) = 1/32)
    const float sc = (mat == 0) ? (1.0f / 32.0f) : 1.0f;
#pragma unroll
    for (int j = 0; j < 8; j++) {
        int c = 8 * j + 2 * tig;
        float2 v0 = make_float2(__uint_as_float(f2tf32(acc[j][0] * sc)),
                                __uint_as_float(f2tf32(acc[j][1] * sc)));
        float2 v1 = make_float2(__uint_as_float(f2tf32(acc[j][2] * sc)),
                                __uint_as_float(f2tf32(acc[j][3] * sc)));
        *reinterpret_cast<float2*>(&dst[(size_t)(m0 + r0) * D_ + c]) = v0;
        *reinterpret_cast<float2*>(&dst[(size_t)(m0 + r1) * D_ + c]) = v1;
    }
}

// ---------------------------------------------------------------------------
// Kernel 2: causal flash attention. Q/K/V arrive tf32-pre-rounded, so the
// QK^T and P@V inner loops carry ZERO cvt instructions.
// 128 threads = 4 warps; warp w owns rows [16w,16w+16) of a 64-row Q tile.
// P@V uses a 2-term P split against tf32 V (drops only the P*Vlo term).
// ---------------------------------------------------------------------------
__global__ __launch_bounds__(128)
void attn_mma_kernel(float* __restrict__ out) {
    __shared__ float KP[64][68];  // K tf32 bits, then P fp32; banks (4g+tig)
    __shared__ float Vs[64][72];  // V tf32 bits; banks (8tig+g)

    const int qt = (int)gridDim.x - 1 - (int)blockIdx.x;  // longest-first
    const int b  = blockIdx.y;
    const int q0 = qt * 64;

    const int tid  = threadIdx.x;
    const int w    = tid >> 5;
    const int lane = tid & 31;
    const int g    = lane >> 2;
    const int tig  = lane & 3;
    const int r0   = 16 * w + g;
    const int r1   = r0 + 8;

    // Stage Q tile through KP, then grab fragments (already scaled+rounded)
    {
        const float* Qg = g_Q + ((size_t)b * T_ + q0) * D_;
#pragma unroll
        for (int it = 0; it < 8; it++) {
            int i  = tid + 128 * it;
            int r  = i >> 4;
            int c4 = i & 15;
            *reinterpret_cast<float4*>(&KP[r][4 * c4]) =
                *reinterpret_cast<const float4*>(&Qg[(size_t)r * D_ + 4 * c4]);
        }
    }
    __syncthreads();

    unsigned qf[8][4];
#pragma unroll
    for (int ks = 0; ks < 8; ks++) {
        const int kc = 8 * ks;
        qf[ks][0] = __float_as_uint(KP[r0][kc + tig]);
        qf[ks][1] = __float_as_uint(KP[r1][kc + tig]);
        qf[ks][2] = __float_as_uint(KP[r0][kc + tig + 4]);
        qf[ks][3] = __float_as_uint(KP[r1][kc + tig + 4]);
    }

    float oacc[8][4];
#pragma unroll
    for (int j = 0; j < 8; j++)
#pragma unroll
        for (int e = 0; e < 4; e++) oacc[j][e] = 0.0f;
    float mr[2] = {-CUDART_INF_F, -CUDART_INF_F};
    float lr[2] = {0.0f, 0.0f};

    for (int jt = 0; jt <= qt; jt++) {
        __syncthreads();  // previous iter's P/V reads (and Q extraction) done

        // Load K and V tiles (tf32 bits): 8 float4 per thread per tile
        {
            const float* Kg = g_K + ((size_t)b * T_ + jt * 64) * D_;
            const float* Vg = g_V + ((size_t)b * T_ + jt * 64) * D_;
#pragma unroll
            for (int it = 0; it < 8; it++) {
                int i  = tid + 128 * it;
                int r  = i >> 4;
                int c4 = i & 15;
                *reinterpret_cast<float4*>(&KP[r][4 * c4]) =
                    *reinterpret_cast<const float4*>(&Kg[(size_t)r * D_ + 4 * c4]);
                *reinterpret_cast<float4*>(&Vs[r][4 * c4]) =
                    *reinterpret_cast<const float4*>(&Vg[(size_t)r * D_ + 4 * c4]);
            }
        }
        __syncthreads();

        // S = Q @ K^T : pure LDS + MMA
        float sacc[8][4];
#pragma unroll
        for (int j = 0; j < 8; j++)
#pragma unroll
            for (int e = 0; e < 4; e++) sacc[j][e] = 0.0f;

#pragma unroll
        for (int ks = 0; ks < 8; ks++) {
            const int kc = 8 * ks;
#pragma unroll
            for (int j = 0; j < 8; j++) {
                unsigned b0 = __float_as_uint(KP[8 * j + g][kc + tig]);
                unsigned b1 = __float_as_uint(KP[8 * j + g][kc + tig + 4]);
                mma_tf32(sacc[j], qf[ks], b0, b1);
            }
        }

        // Causal mask on the diagonal tile
        if (jt == qt) {
#pragma unroll
            for (int j = 0; j < 8; j++) {
                int c = 8 * j + 2 * tig;
                if (c     > r0) sacc[j][0] = -CUDART_INF_F;
                if (c + 1 > r0) sacc[j][1] = -CUDART_INF_F;
                if (c     > r1) sacc[j][2] = -CUDART_INF_F;
                if (c + 1 > r1) sacc[j][3] = -CUDART_INF_F;
            }
        }

        // Online softmax (rows r0, r1; quad shfl covers the other 48 cols)
#pragma unroll
        for (int r = 0; r < 2; r++) {
            const int e0 = 2 * r, e1 = 2 * r + 1;
            float mx = -CUDART_INF_F;
#pragma unroll
            for (int j = 0; j < 8; j++)
                mx = fmaxf(mx, fmaxf(sacc[j][e0], sacc[j][e1]));
            mx = fmaxf(mx, __shfl_xor_sync(0xffffffffu, mx, 1));
            mx = fmaxf(mx, __shfl_xor_sync(0xffffffffu, mx, 2));
            float mn  = fmaxf(mr[r], mx);
            float sum = 0.0f;
#pragma unroll
            for (int j = 0; j < 8; j++) {
                float p0 = __expf(sacc[j][e0] - mn);
                float p1 = __expf(sacc[j][e1] - mn);
                sacc[j][e0] = p0;
                sacc[j][e1] = p1;
                sum += p0 + p1;
            }
            sum += __shfl_xor_sync(0xffffffffu, sum, 1);
            sum += __shfl_xor_sync(0xffffffffu, sum, 2);
            float resc = __expf(mr[r] - mn);  // 0 when mr == -inf
            lr[r] = lr[r] * resc + sum;
            mr[r] = mn;
#pragma unroll
            for (int j = 0; j < 8; j++) {
                oacc[j][e0] *= resc;
                oacc[j][e1] *= resc;
            }
        }

        __syncthreads();  // all warps done reading K from KP

        // Write P into KP (C-fragment layout -> natural row-major)
#pragma unroll
        for (int j = 0; j < 8; j++) {
            int c = 8 * j + 2 * tig;
            *reinterpret_cast<float2*>(&KP[r0][c]) = make_float2(sacc[j][0], sacc[j][1]);
            *reinterpret_cast<float2*>(&KP[r1][c]) = make_float2(sacc[j][2], sacc[j][3]);
        }
        __syncthreads();

        // O += P @ V : 2-term P split vs tf32 V (no cvt on the V side)
#pragma unroll
        for (int ks = 0; ks < 8; ks++) {
            const int kc = 8 * ks;
            unsigned ah[4], al[4];
            split_tf32(KP[r0][kc + tig],     ah[0], al[0]);
            split_tf32(KP[r1][kc + tig],     ah[1], al[1]);
            split_tf32(KP[r0][kc + tig + 4], ah[2], al[2]);
            split_tf32(KP[r1][kc + tig + 4], ah[3], al[3]);
#pragma unroll
            for (int j = 0; j < 8; j++) {
                unsigned b0 = __float_as_uint(Vs[kc + tig][8 * j + g]);
                unsigned b1 = __float_as_uint(Vs[kc + tig + 4][8 * j + g]);
                mma_tf32(oacc[j], ah, b0, b1);
                mma_tf32(oacc[j], al, b0, b1);
            }
        }
    }

    // Final normalize + store
    const float inv0 = 1.0f / lr[0];
    const float inv1 = 1.0f / lr[1];
    float* Og = out + ((size_t)b * T_ + q0) * D_;
#pragma unroll
    for (int j = 0; j < 8; j++) {
        int c = 8 * j + 2 * tig;
        *reinterpret_cast<float2*>(&Og[(size_t)r0 * D_ + c]) =
            make_float2(oacc[j][0] * inv0, oacc[j][1] * inv0);
        *reinterpret_cast<float2*>(&Og[(size_t)r1 * D_ + c]) =
            make_float2(oacc[j][2] * inv1, oacc[j][3] * inv1);
    }
}

// ---------------------------------------------------------------------------
extern "C" void kernel_launch(void* const* d_in, const int* in_sizes, int n_in,
                              void* d_out, int out_size) {
    const float* x  = (const float*)d_in[0];
    const float* Wq = (const float*)d_in[1];
    const float* Wk = (const float*)d_in[2];
    const float* Wv = (const float*)d_in[3];
    float* out = (float*)d_out;

    wsplit_kernel<<<3 * C_ * D_ / 256, 256>>>(Wq, Wk, Wv);
    qkv_mma_kernel<<<dim3((B_ * T_) / PBM, 3), 256>>>(x);
    attn_mma_kernel<<<dim3(T_ / 64, B_), 128>>>(out);
}